// round 1
// baseline (speedup 1.0000x reference)
#include <cuda_runtime.h>

#define B_     2
#define N_IN_  262144
#define D_     32
#define N_OUT_ 65536
#define K_     4
#define NK_    9

// sigma-dedup results (written by prep kernel each launch; deterministic)
__device__ float g_uc[4];    // unique 1/(2*sigma^2) values (fast path: u <= 3)
__device__ int   g_map[32];  // channel -> unique index
__device__ int   g_u;        // number of unique values

__global__ void sigma_prep_kernel(const float* __restrict__ sigma) {
    if (threadIdx.x != 0 || blockIdx.x != 0) return;
    float uc[32];
    int u = 0;
    for (int d = 0; d < D_; d++) {
        float s = sigma[d];
        float c = 1.0f / (2.0f * s * s);
        int f = -1;
        for (int t = 0; t < u; t++) {
            if (uc[t] == c) { f = t; break; }
        }
        if (f < 0) { uc[u] = c; f = u; u++; }
        g_map[d] = f;
    }
    g_u = u;
    for (int t = 0; t < 4; t++) g_uc[t] = (t < u) ? uc[t] : 0.0f;
}

// One warp per (b, n, k) output; lane = channel d.
__global__ void __launch_bounds__(256) proj_kernel(
    const float* __restrict__ x,      // (B, N_IN, D)
    const float* __restrict__ cin,    // (2, B, N_IN)
    const float* __restrict__ cout,   // (2, B, N_OUT, K)
    const float* __restrict__ sigma,  // (D,)
    const int*   __restrict__ nidx,   // (B, N_OUT, K, NK)
    float* __restrict__ out)          // (B, N_OUT*K, D)
{
    const unsigned lane = threadIdx.x & 31u;
    const int bnk = (int)((blockIdx.x * (unsigned)blockDim.x + threadIdx.x) >> 5);
    const int b = bnk >> 18;  // N_OUT*K = 2^18

    // lanes 0..8: load neighbor index, gather coords, compute -d2
    int   myidx = 0;
    float t = 0.0f;
    if (lane < NK_) {
        myidx = __ldg(&nidx[(size_t)bnk * NK_ + lane]);
        float ox = __ldg(&cout[bnk]);
        float oy = __ldg(&cout[bnk + B_ * N_OUT_ * K_]);
        float cx = __ldg(&cin[b * N_IN_ + myidx]);
        float cy = __ldg(&cin[B_ * N_IN_ + b * N_IN_ + myidx]);
        float dx = ox - cx;
        float dy = oy - cy;
        t = -(dx * dx + dy * dy);
    }

    // broadcast neighbor indices, issue all 9 coalesced feature gathers early
    int ij[NK_];
#pragma unroll
    for (int j = 0; j < NK_; j++) ij[j] = __shfl_sync(0xffffffffu, myidx, j);

    const float* xb = x + (size_t)b * N_IN_ * D_ + lane;
    float f[NK_];
#pragma unroll
    for (int j = 0; j < NK_; j++) f[j] = __ldg(xb + (size_t)ij[j] * D_);

    // weights: w[j] for this lane's channel
    const int u  = g_u;
    const int md = g_map[lane];
    float w[NK_];
    if (u <= 3) {
        // lanes (q*9 + jj), q < u, compute exp(t_jj * uc[q]); one EX2 per warp-group
        const int q  = (int)lane / 9;        // 0..3
        const int jj = (int)lane - q * 9;    // 0..8
        float tv = __shfl_sync(0xffffffffu, t, jj);
        float e  = __expf(tv * g_uc[q]);
#pragma unroll
        for (int j = 0; j < NK_; j++)
            w[j] = __shfl_sync(0xffffffffu, e, md * 9 + j);
    } else {
        // general path: per-channel exponent
        float s  = sigma[lane];
        float cd = 1.0f / (2.0f * s * s);
#pragma unroll
        for (int j = 0; j < NK_; j++) {
            float tv = __shfl_sync(0xffffffffu, t, j);
            w[j] = __expf(tv * cd);
        }
    }

    // weighted mean
    float num = 0.0f, den = 1e-9f;
#pragma unroll
    for (int j = 0; j < NK_; j++) {
        num = fmaf(w[j], f[j], num);
        den += w[j];
    }
    out[(size_t)bnk * D_ + lane] = __fdividef(num, den);
}

extern "C" void kernel_launch(void* const* d_in, const int* in_sizes, int n_in,
                              void* d_out, int out_size) {
    const float* x     = (const float*)d_in[0];
    const float* cin   = (const float*)d_in[1];
    const float* cout  = (const float*)d_in[2];
    const float* sigma = (const float*)d_in[3];
    const int*   nidx  = (const int*)d_in[4];
    float* out = (float*)d_out;

    sigma_prep_kernel<<<1, 32>>>(sigma);

    const int total_warps = B_ * N_OUT_ * K_;     // 524288
    const int threads = 256;                      // 8 warps/block
    const int blocks = total_warps / (threads / 32);  // 65536
    proj_kernel<<<blocks, threads>>>(x, cin, cout, sigma, nidx, out);
}

// round 2
// speedup vs baseline: 1.2541x; 1.2541x over previous
#include <cuda_runtime.h>

#define B_     2
#define N_IN_  262144
#define D_     32
#define N_OUT_ 65536
#define K_     4
#define NK_    9
#define TOTAL_ (B_ * N_OUT_ * K_)   // 524288 outputs

// sigma-dedup results
__device__ float g_uc0;      // unique 1/(2*sigma^2) when uniform
__device__ int   g_u;        // number of unique values
// interleaved coords: (cx, cy) per input point
__device__ float2 g_c2[B_ * N_IN_];

__global__ void sigma_prep_kernel(const float* __restrict__ sigma) {
    if (threadIdx.x != 0 || blockIdx.x != 0) return;
    float c0 = 0.0f;
    int u = 0;
    for (int d = 0; d < D_; d++) {
        float s = sigma[d];
        float c = 1.0f / (2.0f * s * s);
        if (u == 0) { c0 = c; u = 1; }
        else if (c != c0) { u = 2; }   // any mismatch -> general path
    }
    g_u   = u;
    g_uc0 = c0;
}

__global__ void pack_coords_kernel(const float* __restrict__ cin) {
    int i = blockIdx.x * blockDim.x + threadIdx.x;
    if (i < B_ * N_IN_) {
        g_c2[i] = make_float2(cin[i], cin[B_ * N_IN_ + i]);
    }
}

// Warp = 2 outputs. lane: g = lane>>4 (which output), sl = lane&15 (channel pair 2*sl, 2*sl+1).
__global__ void __launch_bounds__(256) proj_kernel(
    const float* __restrict__ x,      // (B, N_IN, D)
    const float* __restrict__ cout,   // (2, B, N_OUT, K)
    const float* __restrict__ sigma,  // (D,)
    const int*   __restrict__ nidx,   // (B, N_OUT, K, NK)
    float* __restrict__ out)          // (B, N_OUT*K, D)
{
    const unsigned lane = threadIdx.x & 31u;
    const int w    = (int)((blockIdx.x * (unsigned)blockDim.x + threadIdx.x) >> 5);
    const int bnk0 = w * 2;
    const int g    = (int)(lane >> 4);      // 0 or 1: output within warp
    const int sl   = (int)(lane & 15u);     // channel pair index
    const int bnk  = bnk0 + g;
    const int b    = bnk0 >> 18;            // same b for both outputs (bnk0 even)

    // lanes 0..17: o = lane/9, j = lane%9  -> idx + squared distance for (bnk0+o, j)
    int   myidx = 0;
    float t = 0.0f;
    if (lane < 2 * NK_) {
        const int o = (lane >= NK_) ? 1 : 0;
        const int j = (int)lane - o * NK_;
        const int obnk = bnk0 + o;
        myidx = __ldg(&nidx[(size_t)obnk * NK_ + j]);
        float2 c = g_c2[b * N_IN_ + myidx];
        float ox = __ldg(&cout[obnk]);
        float oy = __ldg(&cout[obnk + TOTAL_]);
        float dx = ox - c.x;
        float dy = oy - c.y;
        t = -(dx * dx + dy * dy);
    }

    // broadcast this output's 9 neighbor indices, issue feature gathers early
    int ij[NK_];
#pragma unroll
    for (int j = 0; j < NK_; j++) ij[j] = __shfl_sync(0xffffffffu, myidx, g * NK_ + j);

    const float2* xb = (const float2*)(x + (size_t)b * N_IN_ * D_) + sl;
    float2 f[NK_];
#pragma unroll
    for (int j = 0; j < NK_; j++) f[j] = __ldg(xb + (size_t)ij[j] * (D_ / 2));

    // weights
    float wj[NK_];
    if (g_u == 1) {
        // uniform sigma: 18 exps computed in lanes 0..17, one MUFU pass warp-wide
        float e = __expf(t * g_uc0);
#pragma unroll
        for (int j = 0; j < NK_; j++)
            wj[j] = __shfl_sync(0xffffffffu, e, g * NK_ + j);
        // accumulate (same weight for both channels in the pair)
        float2 num = make_float2(0.0f, 0.0f);
        float den = 1e-9f;
#pragma unroll
        for (int j = 0; j < NK_; j++) {
            num.x = fmaf(wj[j], f[j].x, num.x);
            num.y = fmaf(wj[j], f[j].y, num.y);
            den += wj[j];
        }
        float inv = __fdividef(1.0f, den);
        float2 r = make_float2(num.x * inv, num.y * inv);
        *((float2*)(out + (size_t)bnk * D_) + sl) = r;
    } else {
        // general path: per-channel sigma (correct for any sigma vector)
        float s0 = sigma[2 * sl], s1 = sigma[2 * sl + 1];
        float c0 = 1.0f / (2.0f * s0 * s0);
        float c1 = 1.0f / (2.0f * s1 * s1);
        float2 num = make_float2(0.0f, 0.0f);
        float den0 = 1e-9f, den1 = 1e-9f;
#pragma unroll
        for (int j = 0; j < NK_; j++) {
            float tv = __shfl_sync(0xffffffffu, t, g * NK_ + j);
            float w0 = __expf(tv * c0);
            float w1 = __expf(tv * c1);
            num.x = fmaf(w0, f[j].x, num.x);
            num.y = fmaf(w1, f[j].y, num.y);
            den0 += w0;
            den1 += w1;
        }
        float2 r = make_float2(__fdividef(num.x, den0), __fdividef(num.y, den1));
        *((float2*)(out + (size_t)bnk * D_) + sl) = r;
    }
}

extern "C" void kernel_launch(void* const* d_in, const int* in_sizes, int n_in,
                              void* d_out, int out_size) {
    const float* x     = (const float*)d_in[0];
    const float* cin   = (const float*)d_in[1];
    const float* cout  = (const float*)d_in[2];
    const float* sigma = (const float*)d_in[3];
    const int*   nidx  = (const int*)d_in[4];
    float* out = (float*)d_out;

    sigma_prep_kernel<<<1, 32>>>(sigma);
    pack_coords_kernel<<<(B_ * N_IN_ + 255) / 256, 256>>>(cin);

    const int total_warps = TOTAL_ / 2;              // 262144 warps, 2 outputs each
    const int threads = 256;                          // 8 warps/block
    const int blocks = total_warps / (threads / 32);  // 32768
    proj_kernel<<<blocks, threads>>>(x, cout, sigma, nidx, out);
}

// round 3
// speedup vs baseline: 1.4824x; 1.1820x over previous
#include <cuda_runtime.h>

#define B_     2
#define N_IN_  262144
#define D_     32
#define N_OUT_ 65536
#define K_     4
#define NK_    9
#define TOTAL_ (B_ * N_OUT_ * K_)   // 524288 outputs

// sigma-dedup results + interleaved coords
__device__ float  g_uc0;              // 1/(2*sigma^2) when uniform
__device__ int    g_u;                // 1 = uniform sigma, 2 = general
__device__ float2 g_c2[B_ * N_IN_];   // (cx, cy) per input point

// One fused prep kernel: warp 0 of block 0 checks sigma uniformity via ballot,
// all threads pack coords (4 points per thread, float4 I/O).
__global__ void __launch_bounds__(256) prep_kernel(
    const float* __restrict__ sigma, const float* __restrict__ cin)
{
    if (blockIdx.x == 0 && threadIdx.x < 32) {
        float s = sigma[threadIdx.x];
        float c = 1.0f / (2.0f * s * s);
        float c0 = __shfl_sync(0xffffffffu, c, 0);
        unsigned same = __ballot_sync(0xffffffffu, c == c0);
        if (threadIdx.x == 0) {
            g_u   = (same == 0xffffffffu) ? 1 : 2;
            g_uc0 = c0;
        }
    }
    int i4 = blockIdx.x * blockDim.x + threadIdx.x;   // 4 points per thread
    if (i4 < (B_ * N_IN_) / 4) {
        float4 cx = ((const float4*)cin)[i4];
        float4 cy = ((const float4*)(cin + B_ * N_IN_))[i4];
        float4* dst = (float4*)g_c2;
        dst[i4 * 2 + 0] = make_float4(cx.x, cy.x, cx.y, cy.y);
        dst[i4 * 2 + 1] = make_float4(cx.z, cy.z, cx.w, cy.w);
    }
}

// Warp = 4 outputs (bnk0..bnk0+3). lane: g = lane>>3 (output), sl = lane&7
// (float4 channel group: channels 4*sl..4*sl+3).
__global__ void __launch_bounds__(256) proj_kernel(
    const float* __restrict__ x,      // (B, N_IN, D)
    const float* __restrict__ cout,   // (2, B, N_OUT, K)
    const float* __restrict__ sigma,  // (D,)
    const int*   __restrict__ nidx,   // (B, N_OUT, K, NK)
    float* __restrict__ out)          // (B, N_OUT*K, D)
{
    const unsigned lane = threadIdx.x & 31u;
    const int w    = (int)((blockIdx.x * (unsigned)blockDim.x + threadIdx.x) >> 5);
    const int bnk0 = w * 4;
    const int g    = (int)(lane >> 3);      // 0..3: output within warp
    const int sl   = (int)(lane & 7u);      // float4 channel group
    const int bnk  = bnk0 + g;
    const int b    = bnk0 >> 18;            // constant within warp

    // Two coord phases: lanes 0..17 handle (output o, neighbor j).
    // Phase A -> outputs bnk0+0, bnk0+1; phase B -> bnk0+2, bnk0+3.
    int   idxA = 0, idxB = 0;
    float tA = 0.0f, tB = 0.0f;
    if (lane < 2 * NK_) {
        const int o = (lane >= NK_) ? 1 : 0;
        const int j = (int)lane - o * NK_;

        const int oA = bnk0 + o;
        idxA = __ldg(&nidx[(size_t)oA * NK_ + j]);
        const int oB = bnk0 + 2 + o;
        idxB = __ldg(&nidx[(size_t)oB * NK_ + j]);

        float2 cA = g_c2[b * N_IN_ + idxA];
        float2 cB = g_c2[b * N_IN_ + idxB];
        float oxA = __ldg(&cout[oA]);
        float oyA = __ldg(&cout[oA + TOTAL_]);
        float oxB = __ldg(&cout[oB]);
        float oyB = __ldg(&cout[oB + TOTAL_]);

        float dxA = oxA - cA.x, dyA = oyA - cA.y;
        float dxB = oxB - cB.x, dyB = oyB - cB.y;
        tA = -(dxA * dxA + dyA * dyA);
        tB = -(dxB * dxB + dyB * dyB);
    }

    // Broadcast this lane's output's 9 neighbor indices; issue gathers early.
    const int selbase = (g & 1) * NK_;
    int ij[NK_];
#pragma unroll
    for (int j = 0; j < NK_; j++) {
        int a  = __shfl_sync(0xffffffffu, idxA, selbase + j);
        int bb = __shfl_sync(0xffffffffu, idxB, selbase + j);
        ij[j] = (g < 2) ? a : bb;
    }

    const float4* xb = (const float4*)(x + (size_t)b * N_IN_ * D_) + sl;
    float4 f[NK_];
#pragma unroll
    for (int j = 0; j < NK_; j++) f[j] = __ldg(xb + (size_t)ij[j] * (D_ / 4));

    float4 num = make_float4(0.f, 0.f, 0.f, 0.f);

    if (g_u == 1) {
        // uniform sigma: 2 MUFU passes warp-wide cover all 36 weights
        float eA = __expf(tA * g_uc0);
        float eB = __expf(tB * g_uc0);
        float den = 1e-9f;
#pragma unroll
        for (int j = 0; j < NK_; j++) {
            float ea = __shfl_sync(0xffffffffu, eA, selbase + j);
            float eb = __shfl_sync(0xffffffffu, eB, selbase + j);
            float wj = (g < 2) ? ea : eb;
            num.x = fmaf(wj, f[j].x, num.x);
            num.y = fmaf(wj, f[j].y, num.y);
            num.z = fmaf(wj, f[j].z, num.z);
            num.w = fmaf(wj, f[j].w, num.w);
            den += wj;
        }
        float inv = __fdividef(1.0f, den);
        float4 r = make_float4(num.x * inv, num.y * inv, num.z * inv, num.w * inv);
        ((float4*)(out + (size_t)bnk * D_))[sl] = r;
    } else {
        // general path: per-channel sigma
        float4 s4 = ((const float4*)sigma)[sl];
        float c0 = 1.0f / (2.0f * s4.x * s4.x);
        float c1 = 1.0f / (2.0f * s4.y * s4.y);
        float c2 = 1.0f / (2.0f * s4.z * s4.z);
        float c3 = 1.0f / (2.0f * s4.w * s4.w);
        float d0 = 1e-9f, d1 = 1e-9f, d2 = 1e-9f, d3 = 1e-9f;
#pragma unroll
        for (int j = 0; j < NK_; j++) {
            float ta = __shfl_sync(0xffffffffu, tA, selbase + j);
            float tb = __shfl_sync(0xffffffffu, tB, selbase + j);
            float tv = (g < 2) ? ta : tb;
            float w0 = __expf(tv * c0);
            float w1 = __expf(tv * c1);
            float w2 = __expf(tv * c2);
            float w3 = __expf(tv * c3);
            num.x = fmaf(w0, f[j].x, num.x);
            num.y = fmaf(w1, f[j].y, num.y);
            num.z = fmaf(w2, f[j].z, num.z);
            num.w = fmaf(w3, f[j].w, num.w);
            d0 += w0; d1 += w1; d2 += w2; d3 += w3;
        }
        float4 r = make_float4(__fdividef(num.x, d0), __fdividef(num.y, d1),
                               __fdividef(num.z, d2), __fdividef(num.w, d3));
        ((float4*)(out + (size_t)bnk * D_))[sl] = r;
    }
}

extern "C" void kernel_launch(void* const* d_in, const int* in_sizes, int n_in,
                              void* d_out, int out_size) {
    const float* x     = (const float*)d_in[0];
    const float* cin   = (const float*)d_in[1];
    const float* cout  = (const float*)d_in[2];
    const float* sigma = (const float*)d_in[3];
    const int*   nidx  = (const int*)d_in[4];
    float* out = (float*)d_out;

    const int prep_items = (B_ * N_IN_) / 4;                    // 131072
    prep_kernel<<<(prep_items + 255) / 256, 256>>>(sigma, cin);

    const int total_warps = TOTAL_ / 4;               // 131072 warps, 4 outputs each
    const int threads = 256;                          // 8 warps/block
    const int blocks = total_warps / (threads / 32);  // 16384
    proj_kernel<<<blocks, threads>>>(x, cout, sigma, nidx, out);
}

// round 4
// speedup vs baseline: 1.4830x; 1.0004x over previous
#include <cuda_runtime.h>
#include <cuda_fp16.h>

#define B_     2
#define N_IN_  262144
#define D_     32
#define N_OUT_ 65536
#define K_     4
#define NK_    9
#define TOTAL_ (B_ * N_OUT_ * K_)   // 524288 outputs

// sigma-dedup results + interleaved coords + fp16 feature copy
__device__ float  g_uc0;                    // 1/(2*sigma^2) when uniform
__device__ int    g_u;                      // 1 = uniform sigma, 2 = general
__device__ float2 g_c2[B_ * N_IN_];         // (cx, cy) per input point
__device__ __half g_xh[B_ * N_IN_ * D_];    // fp16 features, 64B rows

// Fused prep: sigma uniformity (block 0 warp 0), coord pack, fp16 repack.
// Each thread repacks 8 floats (two float4 reads -> one 16B half store).
__global__ void __launch_bounds__(256) prep_kernel(
    const float* __restrict__ x,
    const float* __restrict__ sigma,
    const float* __restrict__ cin)
{
    const int tid = blockIdx.x * blockDim.x + threadIdx.x;

    if (blockIdx.x == 0 && threadIdx.x < 32) {
        float s = sigma[threadIdx.x];
        float c = 1.0f / (2.0f * s * s);
        float c0 = __shfl_sync(0xffffffffu, c, 0);
        unsigned same = __ballot_sync(0xffffffffu, c == c0);
        if (threadIdx.x == 0) {
            g_u   = (same == 0xffffffffu) ? 1 : 2;
            g_uc0 = c0;
        }
    }

    // fp16 repack: 16,777,216 floats / 8 per thread = 2,097,152 threads
    {
        const float4* x4 = (const float4*)x;
        float4 a = __ldg(&x4[tid * 2]);
        float4 bq = __ldg(&x4[tid * 2 + 1]);
        __half2 h0 = __floats2half2_rn(a.x, a.y);
        __half2 h1 = __floats2half2_rn(a.z, a.w);
        __half2 h2 = __floats2half2_rn(bq.x, bq.y);
        __half2 h3 = __floats2half2_rn(bq.z, bq.w);
        uint4 p;
        p.x = *(const unsigned*)&h0;
        p.y = *(const unsigned*)&h1;
        p.z = *(const unsigned*)&h2;
        p.w = *(const unsigned*)&h3;
        ((uint4*)g_xh)[tid] = p;
    }

    // coord pack: first 131072 threads handle 4 points each
    if (tid < (B_ * N_IN_) / 4) {
        float4 cx = __ldg(&((const float4*)cin)[tid]);
        float4 cy = __ldg(&((const float4*)(cin + B_ * N_IN_))[tid]);
        float4* dst = (float4*)g_c2;
        dst[tid * 2 + 0] = make_float4(cx.x, cy.x, cx.y, cy.y);
        dst[tid * 2 + 1] = make_float4(cx.z, cy.z, cx.w, cy.w);
    }
}

// Warp = 4 outputs. lane: g = lane>>3 (output), sl = lane&7 (channels 4sl..4sl+3).
__global__ void __launch_bounds__(256) proj_kernel(
    const float* __restrict__ cout,   // (2, B, N_OUT, K)
    const float* __restrict__ sigma,  // (D,)
    const int*   __restrict__ nidx,   // (B, N_OUT, K, NK)
    float* __restrict__ out)          // (B, N_OUT*K, D)
{
    const unsigned lane = threadIdx.x & 31u;
    const int w    = (int)((blockIdx.x * (unsigned)blockDim.x + threadIdx.x) >> 5);
    const int bnk0 = w * 4;
    const int g    = (int)(lane >> 3);      // 0..3: output within warp
    const int sl   = (int)(lane & 7u);      // channel quad
    const int bnk  = bnk0 + g;
    const int b    = bnk0 >> 18;            // constant within warp

    // lanes 0..17 handle (output o, neighbor j) for phases A (outputs 0,1) and B (2,3)
    int   idxA = 0, idxB = 0;
    float tA = 0.0f, tB = 0.0f;
    if (lane < 2 * NK_) {
        const int o = (lane >= NK_) ? 1 : 0;
        const int j = (int)lane - o * NK_;

        const int oA = bnk0 + o;
        idxA = __ldg(&nidx[(size_t)oA * NK_ + j]);
        const int oB = bnk0 + 2 + o;
        idxB = __ldg(&nidx[(size_t)oB * NK_ + j]);

        float2 cA = g_c2[b * N_IN_ + idxA];
        float2 cB = g_c2[b * N_IN_ + idxB];
        float oxA = __ldg(&cout[oA]);
        float oyA = __ldg(&cout[oA + TOTAL_]);
        float oxB = __ldg(&cout[oB]);
        float oyB = __ldg(&cout[oB + TOTAL_]);

        float dxA = oxA - cA.x, dyA = oyA - cA.y;
        float dxB = oxB - cB.x, dyB = oyB - cB.y;
        tA = -(dxA * dxA + dyA * dyA);
        tB = -(dxB * dxB + dyB * dyB);
    }

    // broadcast neighbor indices, issue fp16 feature gathers (LDG.64) early
    const int selbase = (g & 1) * NK_;
    int ij[NK_];
#pragma unroll
    for (int j = 0; j < NK_; j++) {
        int a  = __shfl_sync(0xffffffffu, idxA, selbase + j);
        int bb = __shfl_sync(0xffffffffu, idxB, selbase + j);
        ij[j] = (g < 2) ? a : bb;
    }

    const uint2* xb = (const uint2*)g_xh + (size_t)b * N_IN_ * (D_ / 4) + sl;
    uint2 f[NK_];
#pragma unroll
    for (int j = 0; j < NK_; j++) f[j] = __ldg(xb + (size_t)ij[j] * (D_ / 4));

    float4 num = make_float4(0.f, 0.f, 0.f, 0.f);

    if (g_u == 1) {
        float eA = __expf(tA * g_uc0);
        float eB = __expf(tB * g_uc0);
        float den = 1e-9f;
#pragma unroll
        for (int j = 0; j < NK_; j++) {
            float ea = __shfl_sync(0xffffffffu, eA, selbase + j);
            float eb = __shfl_sync(0xffffffffu, eB, selbase + j);
            float wj = (g < 2) ? ea : eb;
            float2 lo = __half22float2(*(const __half2*)&f[j].x);
            float2 hi = __half22float2(*(const __half2*)&f[j].y);
            num.x = fmaf(wj, lo.x, num.x);
            num.y = fmaf(wj, lo.y, num.y);
            num.z = fmaf(wj, hi.x, num.z);
            num.w = fmaf(wj, hi.y, num.w);
            den += wj;
        }
        float inv = __fdividef(1.0f, den);
        float4 r = make_float4(num.x * inv, num.y * inv, num.z * inv, num.w * inv);
        ((float4*)(out + (size_t)bnk * D_))[sl] = r;
    } else {
        // general path: per-channel sigma
        float4 s4 = ((const float4*)sigma)[sl];
        float c0 = 1.0f / (2.0f * s4.x * s4.x);
        float c1 = 1.0f / (2.0f * s4.y * s4.y);
        float c2 = 1.0f / (2.0f * s4.z * s4.z);
        float c3 = 1.0f / (2.0f * s4.w * s4.w);
        float d0 = 1e-9f, d1 = 1e-9f, d2 = 1e-9f, d3 = 1e-9f;
#pragma unroll
        for (int j = 0; j < NK_; j++) {
            float ta = __shfl_sync(0xffffffffu, tA, selbase + j);
            float tb = __shfl_sync(0xffffffffu, tB, selbase + j);
            float tv = (g < 2) ? ta : tb;
            float w0 = __expf(tv * c0);
            float w1 = __expf(tv * c1);
            float w2 = __expf(tv * c2);
            float w3 = __expf(tv * c3);
            float2 lo = __half22float2(*(const __half2*)&f[j].x);
            float2 hi = __half22float2(*(const __half2*)&f[j].y);
            num.x = fmaf(w0, lo.x, num.x);
            num.y = fmaf(w1, lo.y, num.y);
            num.z = fmaf(w2, hi.x, num.z);
            num.w = fmaf(w3, hi.y, num.w);
            d0 += w0; d1 += w1; d2 += w2; d3 += w3;
        }
        float4 r = make_float4(__fdividef(num.x, d0), __fdividef(num.y, d1),
                               __fdividef(num.z, d2), __fdividef(num.w, d3));
        ((float4*)(out + (size_t)bnk * D_))[sl] = r;
    }
}

extern "C" void kernel_launch(void* const* d_in, const int* in_sizes, int n_in,
                              void* d_out, int out_size) {
    const float* x     = (const float*)d_in[0];
    const float* cin   = (const float*)d_in[1];
    const float* cout  = (const float*)d_in[2];
    const float* sigma = (const float*)d_in[3];
    const int*   nidx  = (const int*)d_in[4];
    float* out = (float*)d_out;

    const int prep_threads = (B_ * N_IN_ * D_) / 8;   // 2,097,152
    prep_kernel<<<prep_threads / 256, 256>>>(x, sigma, cin);

    const int total_warps = TOTAL_ / 4;               // 131072 warps, 4 outputs each
    const int threads = 256;
    const int blocks = total_warps / (threads / 32);  // 16384
    proj_kernel<<<blocks, threads>>>(cout, sigma, nidx, out);
}